// round 6
// baseline (speedup 1.0000x reference)
#include <cuda_runtime.h>
#include <cuda_bf16.h>
#include <cstdint>
#include <math.h>

// ---------------------------------------------------------------------------
// Problem constants
// ---------------------------------------------------------------------------
#define NB    8          // batch
#define NW    1000       // windows per batch element
#define WS_   25         // window size
#define D0    256        // latent dim
#define H_    128        // hidden channels
#define NWIN  8000       // total windows
#define PADW  32         // padded rows per window (25 data + 7 zero)
#define ROWS_PAD (NWIN*PADW)   // 256000 padded rows

// ---------------------------------------------------------------------------
// Device scratch (static __device__ arrays -- no allocation)
// ---------------------------------------------------------------------------
__device__ __nv_bfloat16 g_w0p[7 * 256 * 128];   // [tap][ci][co]
__device__ __nv_bfloat16 g_w1p[5 * 128 * 128];
__device__ __nv_bfloat16 g_w2p[5 * 128 * 128];
__device__ __nv_bfloat16 g_act0[(size_t)ROWS_PAD * H_];  // padded (win,32,128)
__device__ __nv_bfloat16 g_act1[(size_t)ROWS_PAD * H_];
__device__ float         g_wscore[NWIN];

// ---------------------------------------------------------------------------
// Helpers
// ---------------------------------------------------------------------------
__device__ __forceinline__ float gelu_f(float x) {
    return 0.5f * x * (1.0f + erff(x * 0.70710678118654752f));
}

__device__ __forceinline__ uint32_t smem_u32(const void* p) {
    uint32_t a;
    asm("{ .reg .u64 t; cvta.to.shared.u64 t, %1; cvt.u32.u64 %0, t; }"
        : "=r"(a) : "l"(p));
    return a;
}

__device__ __forceinline__ void cp16(uint32_t dst, const void* src) {
    asm volatile("cp.async.cg.shared.global [%0], [%1], 16;"
                 :: "r"(dst), "l"(src));
}
__device__ __forceinline__ void cp16z(uint32_t dst, const void* src, int sz) {
    asm volatile("cp.async.cg.shared.global [%0], [%1], 16, %2;"
                 :: "r"(dst), "l"(src), "r"(sz));
}
__device__ __forceinline__ void cp_commit() {
    asm volatile("cp.async.commit_group;" ::: "memory");
}
__device__ __forceinline__ void cp_wait0() {
    asm volatile("cp.async.wait_group 0;" ::: "memory");
}

// Fragment load: 2 x ldmatrix.x4 (A) + 4 x ldmatrix.x4.trans (B)
template<int ROWB>
__device__ __forceinline__ void load_frags(
        uint32_t (&a)[2][4], uint32_t (&b)[8][2],
        uint32_t sAu, uint32_t sBcur, int rbase, int koff, int ks,
        int lane, int warp_n) {
    #pragma unroll
    for (int tm = 0; tm < 2; ++tm) {
        int row = rbase + tm * 16 + (lane & 15);
        int kch = koff + ks * 2 + (lane >> 4);
        uint32_t addr = sAu + row * ROWB + (((kch ^ (row & 7))) << 4);
        asm volatile(
            "ldmatrix.sync.aligned.m8n8.x4.shared.b16 {%0,%1,%2,%3}, [%4];"
            : "=r"(a[tm][0]), "=r"(a[tm][1]), "=r"(a[tm][2]), "=r"(a[tm][3])
            : "r"(addr));
    }
    #pragma unroll
    for (int nb = 0; nb < 4; ++nb) {
        int krow = ks * 16 + (lane & 15);
        int nch  = warp_n * 8 + nb * 2 + (lane >> 4);
        uint32_t addr = sBcur + krow * 256 + (((nch ^ (krow & 7))) << 4);
        asm volatile(
            "ldmatrix.sync.aligned.m8n8.x4.trans.shared.b16 {%0,%1,%2,%3}, [%4];"
            : "=r"(b[2 * nb][0]), "=r"(b[2 * nb][1]),
              "=r"(b[2 * nb + 1][0]), "=r"(b[2 * nb + 1][1])
            : "r"(addr));
    }
}

__device__ __forceinline__ void mma16(
        float (&acc)[2][8][4], const uint32_t (&a)[2][4],
        const uint32_t (&b)[8][2]) {
    #pragma unroll
    for (int tm = 0; tm < 2; ++tm)
        #pragma unroll
        for (int tn = 0; tn < 8; ++tn)
            asm volatile(
                "mma.sync.aligned.m16n8k16.row.col.f32.bf16.bf16.f32 "
                "{%0,%1,%2,%3}, {%4,%5,%6,%7}, {%8,%9}, {%0,%1,%2,%3};"
                : "+f"(acc[tm][tn][0]), "+f"(acc[tm][tn][1]),
                  "+f"(acc[tm][tn][2]), "+f"(acc[tm][tn][3])
                : "r"(a[tm][0]), "r"(a[tm][1]), "r"(a[tm][2]), "r"(a[tm][3]),
                  "r"(b[tn][0]), "r"(b[tn][1]));
}

// ---------------------------------------------------------------------------
// Weight prep: transpose conv weights to [tap][ci][co] bf16
// ---------------------------------------------------------------------------
__global__ void prep_weights(const float* __restrict__ w0,
                             const float* __restrict__ w1,
                             const float* __restrict__ w2) {
    int idx = blockIdx.x * blockDim.x + threadIdx.x;
    if (idx < 7 * 256 * 128) {
        int co = idx & 127, ci = (idx >> 7) & 255, tap = idx >> 15;
        g_w0p[idx] = __float2bfloat16(w0[(co * 256 + ci) * 7 + tap]);
    }
    idx -= 7 * 256 * 128;
    if (idx >= 0 && idx < 5 * 128 * 128) {
        int co = idx & 127, ci = (idx >> 7) & 127, tap = idx >> 14;
        g_w1p[idx] = __float2bfloat16(w1[(co * 128 + ci) * 5 + tap]);
        g_w2p[idx] = __float2bfloat16(w2[(co * 128 + ci) * 5 + tap]);
    }
}

// ---------------------------------------------------------------------------
// Fused conv kernel: one CTA = 4 windows (M=128 padded rows), N=128 channels.
// BRES=true : all taps' weights resident in smem; sync-free, fully unrolled,
//             2-deep register-pipelined mainloop (conv1/conv2).
// BRES=false: per-128ci double-buffered cp.async stages (conv0, K too big).
// WSEL: 0 = conv0 (input latents fp32, out g_act0)
//       1 = conv1 (in g_act0, out g_act1)
//       2 = conv2 (in g_act1) -- with HEAD=true: pool + MLP head fused
// ---------------------------------------------------------------------------
template<int C_IN, int TAPS, int WSEL, bool HEAD, bool BRES>
__global__ void __launch_bounds__(256)
conv_kernel(const float* __restrict__ latents,
            const float* __restrict__ bias,
            const float* __restrict__ hw1, const float* __restrict__ hb1,
            const float* __restrict__ hw2, const float* __restrict__ hb2) {
    constexpr int ROWS_A = 144;              // 8 lead zeros + 128 + trailing pad
    constexpr int ROWB   = C_IN * 2;         // bytes per A row
    constexpr int NCH    = C_IN / 8;         // 16B chunks per A row
    constexpr int HALF   = TAPS / 2;
    constexpr int SUBK   = C_IN / 128;       // 128-channel sub-stages per tap
    constexpr int NSTG   = TAPS * SUBK;      // total 128-ci stages
    constexpr int BBUF   = 128 * 256;        // one B stage: 128 rows x 256B
    constexpr int NBUF   = BRES ? NSTG : 2;  // resident B buffers

    extern __shared__ char smem[];
    char* sA_base = smem;                          // ROWS_A * ROWB (swizzled)
    char* sB_base = smem + ROWS_A * ROWB;          // NBUF x BBUF (swizzled)
    float* sFeat  = (float*)(smem + ROWS_A * ROWB + NBUF * BBUF);

    const int tid    = threadIdx.x;
    const int cta    = blockIdx.x;
    const int lane   = tid & 31;
    const int wid    = tid >> 5;
    const int warp_m = wid & 3;    // 4 along M (32 rows each = 1 window)
    const int warp_n = wid >> 2;   // 2 along N (64 cols each)

    const long Vbase = (long)cta * 128 - 8;
    const __nv_bfloat16* wp = (WSEL == 0) ? g_w0p : (WSEL == 1) ? g_w1p : g_w2p;
    const uint32_t sAu = smem_u32(sA_base);
    const uint32_t sBu = smem_u32(sB_base);

    // ---- Issue B prefetch (stage 0, or ALL stages if resident) -----------
    {
        constexpr int NLD = (BRES ? NSTG : 1) * 128 * 16;
        #pragma unroll
        for (int idx = tid; idx < NLD; idx += 256) {
            int ci = idx >> 4, cc = idx & 15;   // ci is global row across stages
            cp16(sBu + ci * 256 + (((cc ^ (ci & 7))) << 4),
                 wp + (size_t)ci * 128 + cc * 8);
        }
        cp_commit();
    }

    // ---- Stage A tile into swizzled smem (bf16) -------------------------
    if constexpr (WSEL == 0) {
        for (int idx = tid; idx < ROWS_A * NCH; idx += 256) {
            int i = idx / NCH, c = idx - i * NCH;
            long V = Vbase + i;
            uint4 pk = make_uint4(0u, 0u, 0u, 0u);
            if (V >= 0 && V < (long)ROWS_PAD) {
                int dr = (int)(V & 31);
                if (dr < WS_) {
                    int win = (int)(V >> 5);
                    int b = win / NW, wi = win - b * NW;
                    const float* src =
                        latents + ((size_t)(b * 25000 + wi * WS_ + dr)) * D0 + c * 8;
                    float4 f0 = *(const float4*)src;
                    float4 f1 = *((const float4*)src + 1);
                    __nv_bfloat162 h0 = __floats2bfloat162_rn(f0.x, f0.y);
                    __nv_bfloat162 h1 = __floats2bfloat162_rn(f0.z, f0.w);
                    __nv_bfloat162 h2 = __floats2bfloat162_rn(f1.x, f1.y);
                    __nv_bfloat162 h3 = __floats2bfloat162_rn(f1.z, f1.w);
                    pk.x = *reinterpret_cast<uint32_t*>(&h0);
                    pk.y = *reinterpret_cast<uint32_t*>(&h1);
                    pk.z = *reinterpret_cast<uint32_t*>(&h2);
                    pk.w = *reinterpret_cast<uint32_t*>(&h3);
                }
            }
            *reinterpret_cast<uint4*>(sA_base + i * ROWB + (((c ^ (i & 7))) << 4)) = pk;
        }
    } else {
        const __nv_bfloat16* actin = (WSEL == 1) ? g_act0 : g_act1;
        #pragma unroll
        for (int idx = tid; idx < ROWS_A * NCH; idx += 256) {
            int i = idx / NCH, c = idx - i * NCH;
            long V = Vbase + i;
            long Vc = V < 0 ? 0 : (V >= (long)ROWS_PAD ? (long)ROWS_PAD - 1 : V);
            int sz = (V >= 0 && V < (long)ROWS_PAD) ? 16 : 0;
            cp16z(sAu + i * ROWB + (((c ^ (i & 7))) << 4),
                  actin + (size_t)Vc * H_ + c * 8, sz);
        }
        cp_commit();
    }

    // ---- Mainloop --------------------------------------------------------
    float acc[2][8][4];
    #pragma unroll
    for (int tm = 0; tm < 2; ++tm)
        #pragma unroll
        for (int tn = 0; tn < 8; ++tn)
            #pragma unroll
            for (int j = 0; j < 4; ++j) acc[tm][tn][j] = 0.0f;

    uint32_t fa[2][2][4];
    uint32_t fb[2][8][2];

    if constexpr (BRES) {
        // Everything resident: one barrier, then a sync-free fully-unrolled
        // register-pipelined stream of TAPS*8 iterations.
        cp_wait0();
        __syncthreads();

        constexpr int NIT = TAPS * 8;
        load_frags<ROWB>(fa[0], fb[0], sAu, sBu, 8 - HALF + warp_m * 32, 0, 0,
                         lane, warp_n);
        #pragma unroll
        for (int it = 0; it < NIT; ++it) {
            if (it + 1 < NIT) {
                int nit = it + 1, ntap = nit >> 3, nks = nit & 7;
                load_frags<ROWB>(fa[(it + 1) & 1], fb[(it + 1) & 1], sAu,
                                 sBu + ntap * BBUF,
                                 8 + ntap - HALF + warp_m * 32, 0, nks,
                                 lane, warp_n);
            }
            mma16(acc, fa[it & 1], fb[it & 1]);
        }
    } else {
        int buf = 0;
        for (int s = 0; s < NSTG; ++s) {
            cp_wait0();
            __syncthreads();   // stage s B (+A on s=0) resident; buf^1 free

            if (s + 1 < NSTG) {  // prefetch next stage into the other buffer
                const __nv_bfloat16* src = wp + (size_t)(s + 1) * 128 * 128;
                uint32_t base = sBu + (buf ^ 1) * BBUF;
                #pragma unroll
                for (int idx = tid; idx < 128 * 16; idx += 256) {
                    int ci = idx >> 4, cc = idx & 15;
                    cp16(base + ci * 256 + (((cc ^ (ci & 7))) << 4),
                         src + (size_t)ci * 128 + cc * 8);
                }
                cp_commit();
            }

            const int tap  = s / SUBK;
            const int koff = (s - tap * SUBK) * 16;       // 8-ch chunk offset
            const int rbase = 8 + tap - HALF + warp_m * 32;
            const uint32_t sBcur = sBu + buf * BBUF;

            load_frags<ROWB>(fa[0], fb[0], sAu, sBcur, rbase, koff, 0,
                             lane, warp_n);
            #pragma unroll
            for (int ks = 0; ks < 8; ++ks) {
                if (ks < 7)
                    load_frags<ROWB>(fa[(ks + 1) & 1], fb[(ks + 1) & 1], sAu,
                                     sBcur, rbase, koff, ks + 1, lane, warp_n);
                mma16(acc, fa[ks & 1], fb[ks & 1]);
            }
            buf ^= 1;
        }
    }

    // ---- Epilogue --------------------------------------------------------
    if constexpr (!HEAD) {
        __nv_bfloat16* actout = (WSEL == 0) ? g_act0 : g_act1;
        #pragma unroll
        for (int tm = 0; tm < 2; ++tm) {
            #pragma unroll
            for (int tn = 0; tn < 8; ++tn) {
                int col = warp_n * 64 + tn * 8 + (lane & 3) * 2;
                float b0 = bias[col], b1v = bias[col + 1];
                #pragma unroll
                for (int jh = 0; jh < 2; ++jh) {
                    int row = warp_m * 32 + tm * 16 + (lane >> 2) + jh * 8;
                    int dr = row & 31;
                    float v0 = 0.0f, v1 = 0.0f;
                    if (dr < WS_) {
                        v0 = gelu_f(acc[tm][tn][jh * 2 + 0] + b0);
                        v1 = gelu_f(acc[tm][tn][jh * 2 + 1] + b1v);
                    }
                    size_t R = (size_t)cta * 128 + row;
                    __nv_bfloat162 h = __floats2bfloat162_rn(v0, v1);
                    *reinterpret_cast<__nv_bfloat162*>(actout + R * H_ + col) = h;
                }
            }
        }
    } else {
        // pooling: each warp owns exactly one window (32 rows) x 64 cols half
        #pragma unroll
        for (int tn = 0; tn < 8; ++tn) {
            #pragma unroll
            for (int jl = 0; jl < 2; ++jl) {
                int col = warp_n * 64 + tn * 8 + (lane & 3) * 2 + jl;
                float bc = bias[col];
                float s = 0.0f;
                #pragma unroll
                for (int tm = 0; tm < 2; ++tm)
                    #pragma unroll
                    for (int jh = 0; jh < 2; ++jh) {
                        int row = warp_m * 32 + tm * 16 + (lane >> 2) + jh * 8;
                        if ((row & 31) < WS_)
                            s += gelu_f(acc[tm][tn][jh * 2 + jl] + bc);
                    }
                s += __shfl_xor_sync(0xffffffffu, s, 4);
                s += __shfl_xor_sync(0xffffffffu, s, 8);
                s += __shfl_xor_sync(0xffffffffu, s, 16);
                if ((lane >> 2) == 0)
                    sFeat[warp_m * 128 + col] = s * (1.0f / WS_);
            }
        }
        __syncthreads();
        if (wid < 4) {  // one warp per window: MLP head
            int win = wid;
            const float* f = sFeat + win * 128;
            float z = 0.0f;
            #pragma unroll
            for (int q = 0; q < 4; ++q) {
                int j = q * 32 + lane;
                float a = hb1[j];
                const float* wrow = hw1 + (size_t)j * 128;
                #pragma unroll 4
                for (int i = 0; i < 128; i += 4) {
                    float4 w = *reinterpret_cast<const float4*>(wrow + i);
                    a += f[i] * w.x + f[i + 1] * w.y + f[i + 2] * w.z + f[i + 3] * w.w;
                }
                z += gelu_f(a) * hw2[j];
            }
            #pragma unroll
            for (int o = 16; o > 0; o >>= 1)
                z += __shfl_xor_sync(0xffffffffu, z, o);
            if (lane == 0) {
                float zz = z + hb2[0];
                g_wscore[cta * 4 + win] = 5.0f / (1.0f + expf(-zz));
            }
        }
    }
}

// ---------------------------------------------------------------------------
// Finalize: mean over batch, threshold, write outputs
// ---------------------------------------------------------------------------
__global__ void finalize_kernel(float* __restrict__ out, int out_size) {
    int wi = blockIdx.x * blockDim.x + threadIdx.x;
    if (wi < NW) {
        float s = 0.0f;
        #pragma unroll
        for (int b = 0; b < NB; ++b) s += g_wscore[b * NW + wi];
        s *= (1.0f / NB);
        out[wi] = s;
        if (out_size >= 2 * NW)
            out[NW + wi] = (s < 3.5f) ? 1.0f : 0.0f;
    }
}

// ---------------------------------------------------------------------------
// Launch
// ---------------------------------------------------------------------------
extern "C" void kernel_launch(void* const* d_in, const int* in_sizes, int n_in,
                              void* d_out, int out_size) {
    const float* latents = (const float*)d_in[0];
    const float* c0w = (const float*)d_in[1];
    const float* c0b = (const float*)d_in[2];
    const float* c1w = (const float*)d_in[3];
    const float* c1b = (const float*)d_in[4];
    const float* c2w = (const float*)d_in[5];
    const float* c2b = (const float*)d_in[6];
    const float* hw1 = (const float*)d_in[7];
    const float* hb1 = (const float*)d_in[8];
    const float* hw2 = (const float*)d_in[9];
    const float* hb2 = (const float*)d_in[10];

    prep_weights<<<304, 1024>>>(c0w, c1w, c2w);

    {   // conv0: staged (K=7x256 too large to keep resident)
        constexpr int SMEM = 144 * 512 + 2 * 128 * 256;  // 139264
        cudaFuncSetAttribute(conv_kernel<256, 7, 0, false, false>,
                             cudaFuncAttributeMaxDynamicSharedMemorySize, SMEM);
        conv_kernel<256, 7, 0, false, false><<<2000, 256, SMEM>>>(
            latents, c0b, nullptr, nullptr, nullptr, nullptr);
    }
    {   // conv1: weights fully resident, sync-free mainloop
        constexpr int SMEM = 144 * 256 + 5 * 128 * 256;  // 200704
        cudaFuncSetAttribute(conv_kernel<128, 5, 1, false, true>,
                             cudaFuncAttributeMaxDynamicSharedMemorySize, SMEM);
        conv_kernel<128, 5, 1, false, true><<<2000, 256, SMEM>>>(
            nullptr, c1b, nullptr, nullptr, nullptr, nullptr);
    }
    {   // conv2 + pool + head
        constexpr int SMEM = 144 * 256 + 5 * 128 * 256 + 4 * 128 * 4;  // 202752
        cudaFuncSetAttribute(conv_kernel<128, 5, 2, true, true>,
                             cudaFuncAttributeMaxDynamicSharedMemorySize, SMEM);
        conv_kernel<128, 5, 2, true, true><<<2000, 256, SMEM>>>(
            nullptr, c2b, hw1, hb1, hw2, hb2);
    }

    finalize_kernel<<<1, 1024>>>((float*)d_out, out_size);
}

// round 7
// speedup vs baseline: 1.3847x; 1.3847x over previous
#include <cuda_runtime.h>
#include <cuda_bf16.h>
#include <cstdint>
#include <math.h>

// ---------------------------------------------------------------------------
// Problem constants
// ---------------------------------------------------------------------------
#define NB    8          // batch
#define NW    1000       // windows per batch element
#define WS_   25         // window size
#define D0    256        // latent dim
#define H_    128        // hidden channels
#define NWIN  8000       // total windows
#define PADW  32         // padded rows per window (25 data + 7 zero)
#define ROWS_PAD (NWIN*PADW)   // 256000 padded rows

// ---------------------------------------------------------------------------
// Device scratch (static __device__ arrays -- no allocation)
// ---------------------------------------------------------------------------
__device__ __nv_bfloat16 g_w0p[7 * 256 * 128];   // [tap][ci][co], taps contiguous
__device__ __nv_bfloat16 g_w1p[5 * 128 * 128];
__device__ __nv_bfloat16 g_w2p[5 * 128 * 128];
__device__ __nv_bfloat16 g_act0[(size_t)ROWS_PAD * H_];  // padded (win,32,128)
__device__ __nv_bfloat16 g_act1[(size_t)ROWS_PAD * H_];
__device__ float         g_wscore[NWIN];

// ---------------------------------------------------------------------------
// Helpers
// ---------------------------------------------------------------------------
__device__ __forceinline__ float gelu_f(float x) {
    return 0.5f * x * (1.0f + erff(x * 0.70710678118654752f));
}

__device__ __forceinline__ uint32_t smem_u32(const void* p) {
    uint32_t a;
    asm("{ .reg .u64 t; cvta.to.shared.u64 t, %1; cvt.u32.u64 %0, t; }"
        : "=r"(a) : "l"(p));
    return a;
}

__device__ __forceinline__ void cp16(uint32_t dst, const void* src) {
    asm volatile("cp.async.cg.shared.global [%0], [%1], 16;"
                 :: "r"(dst), "l"(src));
}
__device__ __forceinline__ void cp16z(uint32_t dst, const void* src, int sz) {
    asm volatile("cp.async.cg.shared.global [%0], [%1], 16, %2;"
                 :: "r"(dst), "l"(src), "r"(sz));
}
__device__ __forceinline__ void cp_commit() {
    asm volatile("cp.async.commit_group;" ::: "memory");
}
__device__ __forceinline__ void cp_wait0() {
    asm volatile("cp.async.wait_group 0;" ::: "memory");
}

// Fragment load: WM x ldmatrix.x4 (A) + 4 x ldmatrix.x4.trans (B)
template<int ROWB, int WM>
__device__ __forceinline__ void load_frags(
        uint32_t (&a)[WM][4], uint32_t (&b)[8][2],
        uint32_t sAu, uint32_t sBcur, int rbase, int koff, int ks,
        int lane, int warp_n) {
    #pragma unroll
    for (int tm = 0; tm < WM; ++tm) {
        int row = rbase + tm * 16 + (lane & 15);
        int kch = koff + ks * 2 + (lane >> 4);
        uint32_t addr = sAu + row * ROWB + (((kch ^ (row & 7))) << 4);
        asm volatile(
            "ldmatrix.sync.aligned.m8n8.x4.shared.b16 {%0,%1,%2,%3}, [%4];"
            : "=r"(a[tm][0]), "=r"(a[tm][1]), "=r"(a[tm][2]), "=r"(a[tm][3])
            : "r"(addr));
    }
    #pragma unroll
    for (int nb = 0; nb < 4; ++nb) {
        int krow = ks * 16 + (lane & 15);
        int nch  = warp_n * 8 + nb * 2 + (lane >> 4);
        uint32_t addr = sBcur + krow * 256 + (((nch ^ (krow & 7))) << 4);
        asm volatile(
            "ldmatrix.sync.aligned.m8n8.x4.trans.shared.b16 {%0,%1,%2,%3}, [%4];"
            : "=r"(b[2 * nb][0]), "=r"(b[2 * nb][1]),
              "=r"(b[2 * nb + 1][0]), "=r"(b[2 * nb + 1][1])
            : "r"(addr));
    }
}

template<int WM>
__device__ __forceinline__ void mma_tile(
        float (&acc)[WM][8][4], const uint32_t (&a)[WM][4],
        const uint32_t (&b)[8][2]) {
    #pragma unroll
    for (int tm = 0; tm < WM; ++tm)
        #pragma unroll
        for (int tn = 0; tn < 8; ++tn)
            asm volatile(
                "mma.sync.aligned.m16n8k16.row.col.f32.bf16.bf16.f32 "
                "{%0,%1,%2,%3}, {%4,%5,%6,%7}, {%8,%9}, {%0,%1,%2,%3};"
                : "+f"(acc[tm][tn][0]), "+f"(acc[tm][tn][1]),
                  "+f"(acc[tm][tn][2]), "+f"(acc[tm][tn][3])
                : "r"(a[tm][0]), "r"(a[tm][1]), "r"(a[tm][2]), "r"(a[tm][3]),
                  "r"(b[tn][0]), "r"(b[tn][1]));
}

// ---------------------------------------------------------------------------
// Weight prep: transpose conv weights to [tap][ci][co] bf16
// ---------------------------------------------------------------------------
__global__ void prep_weights(const float* __restrict__ w0,
                             const float* __restrict__ w1,
                             const float* __restrict__ w2) {
    int idx = blockIdx.x * blockDim.x + threadIdx.x;
    if (idx < 7 * 256 * 128) {
        int co = idx & 127, ci = (idx >> 7) & 255, tap = idx >> 15;
        g_w0p[idx] = __float2bfloat16(w0[(co * 256 + ci) * 7 + tap]);
    }
    idx -= 7 * 256 * 128;
    if (idx >= 0 && idx < 5 * 128 * 128) {
        int co = idx & 127, ci = (idx >> 7) & 127, tap = idx >> 14;
        g_w1p[idx] = __float2bfloat16(w1[(co * 128 + ci) * 5 + tap]);
        g_w2p[idx] = __float2bfloat16(w2[(co * 128 + ci) * 5 + tap]);
    }
}

// ---------------------------------------------------------------------------
// Fused conv kernel: one CTA = 4 windows (M=128 padded rows), N=128 channels.
// Warp tile = (WM*16) x 64.  WM=2 -> 8 warps/CTA, WM=4 -> 4 warps/CTA.
// K pipeline: stages of SROWS input channels, B double-buffered via cp.async.
// WSEL: 0 = conv0 (input latents fp32, out g_act0)
//       1 = conv1 (in g_act0, out g_act1)
//       2 = conv2 (in g_act1) -- with HEAD=true: pool + MLP head fused
// ---------------------------------------------------------------------------
template<int C_IN, int TAPS, int WSEL, bool HEAD, int WM, int SROWS>
__global__ void __launch_bounds__((128 / (WM * 16)) * 64, 2)
conv_kernel(const float* __restrict__ latents,
            const float* __restrict__ bias,
            const float* __restrict__ hw1, const float* __restrict__ hb1,
            const float* __restrict__ hw2, const float* __restrict__ hb2) {
    constexpr int NWARP_M = 128 / (WM * 16);     // 4 (WM=2) or 2 (WM=4)
    constexpr int NTHR    = NWARP_M * 64;        // 256 or 128
    constexpr int ROWS_A  = 144;                 // 8 lead zeros + 128 + trail
    constexpr int ROWB    = C_IN * 2;            // bytes per A row
    constexpr int NCH     = C_IN / 8;            // 16B chunks per A row
    constexpr int HALF    = TAPS / 2;
    constexpr int SUBK    = C_IN / SROWS;        // sub-stages per tap
    constexpr int NSTG    = TAPS * SUBK;
    constexpr int KSPS    = SROWS / 16;          // ks iters per stage
    constexpr int BBUF    = SROWS * 256;         // one B stage buffer

    extern __shared__ char smem[];
    char* sA_base = smem;                          // ROWS_A * ROWB (swizzled)
    char* sB_base = smem + ROWS_A * ROWB;          // 2 x BBUF (swizzled)
    float* sFeat  = (float*)(smem + ROWS_A * ROWB + 2 * BBUF);

    const int tid    = threadIdx.x;
    const int cta    = blockIdx.x;
    const int lane   = tid & 31;
    const int wid    = tid >> 5;
    const int warp_m = wid % NWARP_M;
    const int warp_n = wid / NWARP_M;

    const long Vbase = (long)cta * 128 - 8;
    const __nv_bfloat16* wp = (WSEL == 0) ? g_w0p : (WSEL == 1) ? g_w1p : g_w2p;
    const uint32_t sAu = smem_u32(sA_base);
    const uint32_t sBu = smem_u32(sB_base);

    // ---- Issue B stage-0 prefetch ----------------------------------------
    #pragma unroll
    for (int idx = tid; idx < SROWS * 16; idx += NTHR) {
        int ci = idx >> 4, cc = idx & 15;
        cp16(sBu + ci * 256 + (((cc ^ (ci & 7))) << 4),
             wp + (size_t)ci * 128 + cc * 8);
    }
    cp_commit();

    // ---- Stage A tile into swizzled smem (bf16) -------------------------
    if constexpr (WSEL == 0) {
        for (int idx = tid; idx < ROWS_A * NCH; idx += NTHR) {
            int i = idx / NCH, c = idx - i * NCH;
            long V = Vbase + i;
            uint4 pk = make_uint4(0u, 0u, 0u, 0u);
            if (V >= 0 && V < (long)ROWS_PAD) {
                int dr = (int)(V & 31);
                if (dr < WS_) {
                    int win = (int)(V >> 5);
                    int b = win / NW, wi = win - b * NW;
                    const float* src =
                        latents + ((size_t)(b * 25000 + wi * WS_ + dr)) * D0 + c * 8;
                    float4 f0 = *(const float4*)src;
                    float4 f1 = *((const float4*)src + 1);
                    __nv_bfloat162 h0 = __floats2bfloat162_rn(f0.x, f0.y);
                    __nv_bfloat162 h1 = __floats2bfloat162_rn(f0.z, f0.w);
                    __nv_bfloat162 h2 = __floats2bfloat162_rn(f1.x, f1.y);
                    __nv_bfloat162 h3 = __floats2bfloat162_rn(f1.z, f1.w);
                    pk.x = *reinterpret_cast<uint32_t*>(&h0);
                    pk.y = *reinterpret_cast<uint32_t*>(&h1);
                    pk.z = *reinterpret_cast<uint32_t*>(&h2);
                    pk.w = *reinterpret_cast<uint32_t*>(&h3);
                }
            }
            *reinterpret_cast<uint4*>(sA_base + i * ROWB + (((c ^ (i & 7))) << 4)) = pk;
        }
    } else {
        const __nv_bfloat16* actin = (WSEL == 1) ? g_act0 : g_act1;
        #pragma unroll
        for (int idx = tid; idx < ROWS_A * NCH; idx += NTHR) {
            int i = idx / NCH, c = idx - i * NCH;
            long V = Vbase + i;
            long Vc = V < 0 ? 0 : (V >= (long)ROWS_PAD ? (long)ROWS_PAD - 1 : V);
            int sz = (V >= 0 && V < (long)ROWS_PAD) ? 16 : 0;
            cp16z(sAu + i * ROWB + (((c ^ (i & 7))) << 4),
                  actin + (size_t)Vc * H_ + c * 8, sz);
        }
        cp_commit();
    }

    // ---- Pipelined mainloop over stages ---------------------------------
    float acc[WM][8][4];
    #pragma unroll
    for (int tm = 0; tm < WM; ++tm)
        #pragma unroll
        for (int tn = 0; tn < 8; ++tn)
            #pragma unroll
            for (int j = 0; j < 4; ++j) acc[tm][tn][j] = 0.0f;

    uint32_t fa[2][WM][4];
    uint32_t fb[2][8][2];

    int buf = 0;
    for (int s = 0; s < NSTG; ++s) {
        cp_wait0();
        __syncthreads();   // stage s B (+A on s=0) resident; buf^1 free

        if (s + 1 < NSTG) {  // prefetch next stage into the other buffer
            const __nv_bfloat16* src = wp + (size_t)(s + 1) * SROWS * 128;
            uint32_t base = sBu + (buf ^ 1) * BBUF;
            #pragma unroll
            for (int idx = tid; idx < SROWS * 16; idx += NTHR) {
                int ci = idx >> 4, cc = idx & 15;
                cp16(base + ci * 256 + (((cc ^ (ci & 7))) << 4),
                     src + (size_t)ci * 128 + cc * 8);
            }
            cp_commit();
        }

        const int tap  = s / SUBK;
        const int sub  = s - tap * SUBK;
        const int koff = sub * (SROWS / 8);          // 8-ch chunk offset
        const int rbase = 8 + tap - HALF + warp_m * (WM * 16);
        const uint32_t sBcur = sBu + buf * BBUF;

        load_frags<ROWB, WM>(fa[0], fb[0], sAu, sBcur, rbase, koff, 0,
                             lane, warp_n);
        #pragma unroll
        for (int ks = 0; ks < KSPS; ++ks) {
            if (ks + 1 < KSPS)
                load_frags<ROWB, WM>(fa[(ks + 1) & 1], fb[(ks + 1) & 1], sAu,
                                     sBcur, rbase, koff, ks + 1, lane, warp_n);
            mma_tile<WM>(acc, fa[ks & 1], fb[ks & 1]);
        }
        buf ^= 1;
    }

    // ---- Epilogue --------------------------------------------------------
    if constexpr (!HEAD) {
        __nv_bfloat16* actout = (WSEL == 0) ? g_act0 : g_act1;
        #pragma unroll
        for (int tm = 0; tm < WM; ++tm) {
            #pragma unroll
            for (int tn = 0; tn < 8; ++tn) {
                int col = warp_n * 64 + tn * 8 + (lane & 3) * 2;
                float b0 = bias[col], b1v = bias[col + 1];
                #pragma unroll
                for (int jh = 0; jh < 2; ++jh) {
                    int row = warp_m * (WM * 16) + tm * 16 + (lane >> 2) + jh * 8;
                    int dr = row & 31;
                    float v0 = 0.0f, v1 = 0.0f;
                    if (dr < WS_) {
                        v0 = gelu_f(acc[tm][tn][jh * 2 + 0] + b0);
                        v1 = gelu_f(acc[tm][tn][jh * 2 + 1] + b1v);
                    }
                    size_t R = (size_t)cta * 128 + row;
                    __nv_bfloat162 h = __floats2bfloat162_rn(v0, v1);
                    *reinterpret_cast<__nv_bfloat162*>(actout + R * H_ + col) = h;
                }
            }
        }
    } else {
        // HEAD path runs with WM=4 (4 warps). Each warp holds 2 windows
        // (64 rows) x 64 cols. Pool over the 25 valid rows per window.
        static_assert(!HEAD || WM == 4, "head assumes 4-warp layout");
        #pragma unroll
        for (int tn = 0; tn < 8; ++tn) {
            #pragma unroll
            for (int jl = 0; jl < 2; ++jl) {
                int col = warp_n * 64 + tn * 8 + (lane & 3) * 2 + jl;
                float bc = bias[col];
                #pragma unroll
                for (int wh = 0; wh < 2; ++wh) {   // window within warp
                    float s = 0.0f;
                    #pragma unroll
                    for (int tme = 0; tme < 2; ++tme) {
                        int tm = wh * 2 + tme;
                        #pragma unroll
                        for (int jh = 0; jh < 2; ++jh) {
                            int rowin = tme * 16 + (lane >> 2) + jh * 8;
                            if (rowin < WS_)
                                s += gelu_f(acc[tm][tn][jh * 2 + jl] + bc);
                        }
                    }
                    s += __shfl_xor_sync(0xffffffffu, s, 4);
                    s += __shfl_xor_sync(0xffffffffu, s, 8);
                    s += __shfl_xor_sync(0xffffffffu, s, 16);
                    if ((lane >> 2) == 0)
                        sFeat[(warp_m * 2 + wh) * 128 + col] = s * (1.0f / WS_);
                }
            }
        }
        __syncthreads();
        {   // one warp per window: MLP head (4 warps, 4 windows)
            int win = wid;
            const float* f = sFeat + win * 128;
            float z = 0.0f;
            #pragma unroll
            for (int q = 0; q < 4; ++q) {
                int j = q * 32 + lane;
                float a = hb1[j];
                const float* wrow = hw1 + (size_t)j * 128;
                #pragma unroll 4
                for (int i = 0; i < 128; i += 4) {
                    float4 w = *reinterpret_cast<const float4*>(wrow + i);
                    a += f[i] * w.x + f[i + 1] * w.y + f[i + 2] * w.z + f[i + 3] * w.w;
                }
                z += gelu_f(a) * hw2[j];
            }
            #pragma unroll
            for (int o = 16; o > 0; o >>= 1)
                z += __shfl_xor_sync(0xffffffffu, z, o);
            if (lane == 0) {
                float zz = z + hb2[0];
                g_wscore[cta * 4 + win] = 5.0f / (1.0f + expf(-zz));
            }
        }
    }
}

// ---------------------------------------------------------------------------
// Finalize: mean over batch, threshold, write outputs
// ---------------------------------------------------------------------------
__global__ void finalize_kernel(float* __restrict__ out, int out_size) {
    int wi = blockIdx.x * blockDim.x + threadIdx.x;
    if (wi < NW) {
        float s = 0.0f;
        #pragma unroll
        for (int b = 0; b < NB; ++b) s += g_wscore[b * NW + wi];
        s *= (1.0f / NB);
        out[wi] = s;
        if (out_size >= 2 * NW)
            out[NW + wi] = (s < 3.5f) ? 1.0f : 0.0f;
    }
}

// ---------------------------------------------------------------------------
// Launch
// ---------------------------------------------------------------------------
extern "C" void kernel_launch(void* const* d_in, const int* in_sizes, int n_in,
                              void* d_out, int out_size) {
    const float* latents = (const float*)d_in[0];
    const float* c0w = (const float*)d_in[1];
    const float* c0b = (const float*)d_in[2];
    const float* c1w = (const float*)d_in[3];
    const float* c1b = (const float*)d_in[4];
    const float* c2w = (const float*)d_in[5];
    const float* c2b = (const float*)d_in[6];
    const float* hw1 = (const float*)d_in[7];
    const float* hb1 = (const float*)d_in[8];
    const float* hw2 = (const float*)d_in[9];
    const float* hb2 = (const float*)d_in[10];

    prep_weights<<<304, 1024>>>(c0w, c1w, c2w);

    {   // conv0: 8 warps (M32xN64), 64-ci stages -> 106.5KB smem, 2 CTAs/SM
        constexpr int SMEM = 144 * 512 + 2 * 64 * 256;  // 106496
        cudaFuncSetAttribute(conv_kernel<256, 7, 0, false, 2, 64>,
                             cudaFuncAttributeMaxDynamicSharedMemorySize, SMEM);
        conv_kernel<256, 7, 0, false, 2, 64><<<2000, 256, SMEM>>>(
            latents, c0b, nullptr, nullptr, nullptr, nullptr);
    }
    {   // conv1: 4 warps (M64xN64), 128-ci stages -> 102.4KB smem, 2 CTAs/SM
        constexpr int SMEM = 144 * 256 + 2 * 128 * 256;  // 102400
        cudaFuncSetAttribute(conv_kernel<128, 5, 1, false, 4, 128>,
                             cudaFuncAttributeMaxDynamicSharedMemorySize, SMEM);
        conv_kernel<128, 5, 1, false, 4, 128><<<2000, 128, SMEM>>>(
            nullptr, c1b, nullptr, nullptr, nullptr, nullptr);
    }
    {   // conv2 + pool + head: same tiling as conv1
        constexpr int SMEM = 144 * 256 + 2 * 128 * 256 + 4 * 128 * 4;  // 104448
        cudaFuncSetAttribute(conv_kernel<128, 5, 2, true, 4, 128>,
                             cudaFuncAttributeMaxDynamicSharedMemorySize, SMEM);
        conv_kernel<128, 5, 2, true, 4, 128><<<2000, 128, SMEM>>>(
            nullptr, c2b, hw1, hb1, hw2, hb2);
    }

    finalize_kernel<<<1, 1024>>>((float*)d_out, out_size);
}